// round 5
// baseline (speedup 1.0000x reference)
#include <cuda_runtime.h>
#include <cuda_fp16.h>
#include <math.h>

#define N_NODES 50000
#define E_EDGES 1600000
#define B_BATCH 64
#define NB (N_NODES * B_BATCH)

// ---------------------------------------------------------------------------
// Scratch (__device__ globals; no allocation allowed)
// ---------------------------------------------------------------------------
__device__ __align__(16) __half g_xt[NB];     // x node-major fp16 [N][64], 6.4MB
__device__ __align__(16) float  g_msg_r[NB];  // reaction messages  [N][64]
__device__ __align__(16) float  g_msg_d[NB];  // diffusion messages [N][64]
__device__ float g_col_r[N_NODES];
__device__ float g_col_d[N_NODES];
__device__ int   g_cnt_i[N_NODES];            // histogram, then scatter cursor
__device__ int   g_cnt_j[N_NODES];
__device__ int   g_off_i[N_NODES + 1];
__device__ int   g_off_j[N_NODES + 1];
__device__ __align__(16) int4 g_csr_i[E_EDGES];  // {nbr=j, wr, wd, 0} grouped by i
__device__ __align__(16) int4 g_csr_j[E_EDGES];  // {nbr=i, wr, wd, 0} grouped by j

// ---------------------------------------------------------------------------
// 1. Zero the counters (cursor arrays). msg/col are fully overwritten later.
// ---------------------------------------------------------------------------
__global__ void zero_kernel() {
    int tid = blockIdx.x * blockDim.x + threadIdx.x;
    if (tid < N_NODES) { g_cnt_i[tid] = 0; g_cnt_j[tid] = 0; }
}

// ---------------------------------------------------------------------------
// 2. Degree histogram over both groupings
// ---------------------------------------------------------------------------
__global__ void hist_kernel(const int* __restrict__ ei,
                            const int* __restrict__ ej) {
    int e = blockIdx.x * blockDim.x + threadIdx.x;
    if (e >= E_EDGES) return;
    atomicAdd(&g_cnt_i[ei[e]], 1);
    atomicAdd(&g_cnt_j[ej[e]], 1);
}

// ---------------------------------------------------------------------------
// 3. Exclusive scan of counts -> offsets (one block per array, 1024 threads).
//    Also re-initializes cnt[] as the scatter cursor (= starting offset).
// ---------------------------------------------------------------------------
__global__ void scan_kernel() {
    int* cnt = blockIdx.x ? g_cnt_j : g_cnt_i;
    int* off = blockIdx.x ? g_off_j : g_off_i;
    const int CH = (N_NODES + 1023) / 1024;   // 49
    int tid = threadIdx.x;
    int lo = tid * CH;
    int hi = min(lo + CH, N_NODES);

    int s = 0;
    for (int k = lo; k < hi; k++) s += cnt[k];

    __shared__ int sh[1024];
    sh[tid] = s;
    __syncthreads();
    // Hillis-Steele inclusive scan
    for (int d = 1; d < 1024; d <<= 1) {
        int t = (tid >= d) ? sh[tid - d] : 0;
        __syncthreads();
        sh[tid] += t;
        __syncthreads();
    }
    int running = (tid == 0) ? 0 : sh[tid - 1];
    for (int k = lo; k < hi; k++) {
        int c = cnt[k];
        off[k] = running;
        cnt[k] = running;   // cursor init
        running += c;
    }
    if (tid == 1023) off[N_NODES] = sh[1023];
}

// ---------------------------------------------------------------------------
// 4. Scatter edges into both CSR structures
// ---------------------------------------------------------------------------
__global__ void scatter_kernel(const int* __restrict__ ei,
                               const int* __restrict__ ej,
                               const float* __restrict__ wr,
                               const float* __restrict__ wd) {
    int e = blockIdx.x * blockDim.x + threadIdx.x;
    if (e >= E_EDGES) return;
    int i = ei[e], j = ej[e];
    int w1 = __float_as_int(wr[e]);
    int w2 = __float_as_int(wd[e]);
    int p = atomicAdd(&g_cnt_i[i], 1);
    g_csr_i[p] = make_int4(j, w1, w2, 0);
    int q = atomicAdd(&g_cnt_j[j], 1);
    g_csr_j[q] = make_int4(i, w1, w2, 0);
}

// ---------------------------------------------------------------------------
// 5. Transpose x [B, N] -> g_xt [N][64] fp16
// ---------------------------------------------------------------------------
__global__ void transpose_kernel(const float* __restrict__ x) {
    __shared__ float tile[32][33];
    int v0 = blockIdx.x * 32;
    int b0 = blockIdx.y * 32;
    int tx = threadIdx.x;   // 0..31
    int ty = threadIdx.y;   // 0..7

    #pragma unroll
    for (int r = 0; r < 32; r += 8) {
        int b = b0 + ty + r;
        int v = v0 + tx;
        if (v < N_NODES)
            tile[ty + r][tx] = x[(long)b * N_NODES + v];
    }
    __syncthreads();
    #pragma unroll
    for (int r = 0; r < 32; r += 8) {
        int v = v0 + ty + r;
        int b = b0 + tx;
        if (v < N_NODES)
            g_xt[v * B_BATCH + b] = __float2half_rn(tile[tx][ty + r]);
    }
}

// ---------------------------------------------------------------------------
// 6. Gather: 16 threads per node, 4 batch lanes each, fp32 accumulators.
//    REACT=true : CSR-by-i -> msg_r[i] = sum wr * x[j],  col_d[i] = sum wd
//    REACT=false: CSR-by-j -> msg_d[j] = sum wd * x[i],  col_r[j] = sum wr
// ---------------------------------------------------------------------------
template <bool REACT>
__global__ void gather_kernel() {
    int g = blockIdx.x * 16 + (threadIdx.x >> 4);   // node
    int q = threadIdx.x & 15;                       // 4-batch chunk
    if (g >= N_NODES) return;

    const int* off = REACT ? g_off_i : g_off_j;
    const int4* __restrict__ csr = REACT ? g_csr_i : g_csr_j;
    int s  = off[g];
    int e2 = off[g + 1];

    float4 acc = make_float4(0.f, 0.f, 0.f, 0.f);
    float colw = 0.f;

    for (int p = s; p < e2; p++) {
        int4 ent = csr[p];
        int nbr = ent.x;
        float wm = __int_as_float(REACT ? ent.y : ent.z);  // message weight
        float wc = __int_as_float(REACT ? ent.z : ent.y);  // column-sum weight
        uint2 h4 = *reinterpret_cast<const uint2*>(&g_xt[nbr * B_BATCH + q * 4]);
        float2 fa = __half22float2(*reinterpret_cast<__half2*>(&h4.x));
        float2 fb = __half22float2(*reinterpret_cast<__half2*>(&h4.y));
        acc.x = fmaf(wm, fa.x, acc.x);
        acc.y = fmaf(wm, fa.y, acc.y);
        acc.z = fmaf(wm, fb.x, acc.z);
        acc.w = fmaf(wm, fb.y, acc.w);
        colw += wc;
    }

    float* msg = REACT ? g_msg_r : g_msg_d;
    *reinterpret_cast<float4*>(&msg[g * B_BATCH + q * 4]) = acc;
    if (q == 0) {
        if (REACT) g_col_d[g] = colw;
        else       g_col_r[g] = colw;
    }
}

// ---------------------------------------------------------------------------
// 7. Epilogue: fp32 x from original input (batch-major) via smem transpose,
//    compute tanh(reaction)+diffusion+x, write out [B, N] coalesced.
// ---------------------------------------------------------------------------
__global__ void final_kernel(const float* __restrict__ x,
                             const float* __restrict__ bias_r,
                             const float* __restrict__ bias_d,
                             float* __restrict__ out) {
    __shared__ float sx[32 * 65];   // x tile, node-major
    __shared__ float so[32 * 65];   // out tile
    int V0 = blockIdx.x * 32;
    int tid = threadIdx.x;          // 0..511

    // load x tile: b = tid/8, vg = tid%8 (4 nodes each), coalesced float4
    {
        int b  = tid >> 3;
        int vg = tid & 7;
        int vbase = V0 + vg * 4;
        if (vbase + 3 < N_NODES) {
            float4 xv = *reinterpret_cast<const float4*>(&x[(long)b * N_NODES + vbase]);
            sx[(vg * 4 + 0) * 65 + b] = xv.x;
            sx[(vg * 4 + 1) * 65 + b] = xv.y;
            sx[(vg * 4 + 2) * 65 + b] = xv.z;
            sx[(vg * 4 + 3) * 65 + b] = xv.w;
        } else {
            for (int k = 0; k < 4 && vbase + k < N_NODES; k++)
                sx[(vg * 4 + k) * 65 + b] = x[(long)b * N_NODES + vbase + k];
        }
    }
    __syncthreads();

    // compute: vl = node in tile, q = 4-batch chunk
    {
        int vl = tid >> 4;
        int q  = tid & 15;
        int v  = V0 + vl;
        if (v < N_NODES) {
            float4 mr = *reinterpret_cast<const float4*>(&g_msg_r[v * B_BATCH + q * 4]);
            float4 md = *reinterpret_cast<const float4*>(&g_msg_d[v * B_BATCH + q * 4]);
            float cr = g_col_r[v];
            float cd = g_col_d[v];
            float b1 = bias_r[v];
            float b2 = bias_d[v];
            float ms[4] = {mr.x, mr.y, mr.z, mr.w};
            float dd[4] = {md.x, md.y, md.z, md.w};
            #pragma unroll
            for (int k = 0; k < 4; k++) {
                float xv = sx[vl * 65 + q * 4 + k];
                float reac = fmaf(cr, xv, -ms[k]) + b1;
                float diff = fmaf(cd, xv, -dd[k]) + b2;
                so[vl * 65 + q * 4 + k] = tanhf(reac) + diff + xv;
            }
        }
    }
    __syncthreads();

    // write out: b = tid/8, vg = tid%8, coalesced float4 along v
    {
        int b  = tid >> 3;
        int vg = tid & 7;
        int vbase = V0 + vg * 4;
        if (vbase + 3 < N_NODES) {
            float4 o;
            o.x = so[(vg * 4 + 0) * 65 + b];
            o.y = so[(vg * 4 + 1) * 65 + b];
            o.z = so[(vg * 4 + 2) * 65 + b];
            o.w = so[(vg * 4 + 3) * 65 + b];
            *reinterpret_cast<float4*>(&out[(long)b * N_NODES + vbase]) = o;
        } else if (vbase < N_NODES) {
            for (int k = 0; k < 4 && vbase + k < N_NODES; k++)
                out[(long)b * N_NODES + vbase + k] = so[(vg * 4 + k) * 65 + b];
        }
    }
}

// ---------------------------------------------------------------------------
extern "C" void kernel_launch(void* const* d_in, const int* in_sizes, int n_in,
                              void* d_out, int out_size) {
    // order: t, input, edge_i, edge_j, weight_react, weight_diff,
    //        bias_reaction, bias_diffusion
    const float* x  = (const float*)d_in[1];
    const int*   ei = (const int*)d_in[2];
    const int*   ej = (const int*)d_in[3];
    const float* wr = (const float*)d_in[4];
    const float* wd = (const float*)d_in[5];
    const float* br = (const float*)d_in[6];
    const float* bd = (const float*)d_in[7];
    float* out = (float*)d_out;

    zero_kernel<<<(N_NODES + 255) / 256, 256>>>();
    hist_kernel<<<(E_EDGES + 255) / 256, 256>>>(ei, ej);
    scan_kernel<<<2, 1024>>>();
    scatter_kernel<<<(E_EDGES + 255) / 256, 256>>>(ei, ej, wr, wd);

    dim3 tg((N_NODES + 31) / 32, B_BATCH / 32);
    transpose_kernel<<<tg, dim3(32, 8)>>>(x);

    gather_kernel<true ><<<(N_NODES + 15) / 16, 256>>>();
    gather_kernel<false><<<(N_NODES + 15) / 16, 256>>>();

    final_kernel<<<(N_NODES + 31) / 32, 512>>>(x, br, bd, out);
}

// round 6
// speedup vs baseline: 2.3692x; 2.3692x over previous
#include <cuda_runtime.h>
#include <cuda_fp16.h>
#include <math.h>

#define N_NODES 50000
#define E_EDGES 1600000
#define B_BATCH 64
#define NB (N_NODES * B_BATCH)

// ---------------------------------------------------------------------------
// Scratch (__device__ globals; allocation-free). All fp16, 16B-aligned for
// uint4 loads and red.global.add.noftz.v4.f16x2 (misalign = err715 trap).
// ---------------------------------------------------------------------------
__device__ __align__(16) __half g_xt[NB];      // x node-major fp16 [N][64]
__device__ __align__(16) __half g_msg_r[NB];   // reaction messages  (fp16 accum)
__device__ __align__(16) __half g_msg_d[NB];   // diffusion messages (fp16 accum)
__device__ float g_col_r[N_NODES];
__device__ float g_col_d[N_NODES];

__device__ __forceinline__ void red_v4_f16x2(__half* p, uint4 v) {
    unsigned long long gp;
    asm("cvta.to.global.u64 %0, %1;" : "=l"(gp) : "l"(p));
    asm volatile("red.global.add.noftz.v4.f16x2 [%0], {%1,%2,%3,%4};"
                 :: "l"(gp), "r"(v.x), "r"(v.y), "r"(v.z), "r"(v.w)
                 : "memory");
}

// scale 8 halves (uint4) by fp32 w, fp32 intermediate math, repack to f16x2
__device__ __forceinline__ uint4 scale8h(uint4 h, float w) {
    uint4 r;
    const unsigned* hp = &h.x;
    unsigned* rp = &r.x;
    #pragma unroll
    for (int k = 0; k < 4; k++) {
        float2 f = __half22float2(*reinterpret_cast<const __half2*>(&hp[k]));
        f.x *= w; f.y *= w;
        *reinterpret_cast<__half2*>(&rp[k]) = __float22half2_rn(f);
    }
    return r;
}

// ---------------------------------------------------------------------------
// 1. Zero accumulators (graph-replay safe: runs every iteration)
// ---------------------------------------------------------------------------
__global__ void zero_kernel() {
    int tid = blockIdx.x * blockDim.x + threadIdx.x;
    const int Q = NB / 8;   // uint4 (8 halves) per msg buffer = 400000
    uint4 z = make_uint4(0, 0, 0, 0);
    if (tid < Q) {
        reinterpret_cast<uint4*>(g_msg_r)[tid] = z;
    } else if (tid < 2 * Q) {
        reinterpret_cast<uint4*>(g_msg_d)[tid - Q] = z;
    } else if (tid < 2 * Q + N_NODES) {
        g_col_r[tid - 2 * Q] = 0.f;
    } else if (tid < 2 * Q + 2 * N_NODES) {
        g_col_d[tid - 2 * Q - N_NODES] = 0.f;
    }
}

// ---------------------------------------------------------------------------
// 2. Transpose x [B, N] -> g_xt [N][64] fp16
// ---------------------------------------------------------------------------
__global__ void transpose_kernel(const float* __restrict__ x) {
    __shared__ float tile[32][33];
    int v0 = blockIdx.x * 32;
    int b0 = blockIdx.y * 32;
    int tx = threadIdx.x;   // 0..31
    int ty = threadIdx.y;   // 0..7

    #pragma unroll
    for (int r = 0; r < 32; r += 8) {
        int b = b0 + ty + r;
        int v = v0 + tx;
        if (v < N_NODES)
            tile[ty + r][tx] = x[(long)b * N_NODES + v];
    }
    __syncthreads();
    #pragma unroll
    for (int r = 0; r < 32; r += 8) {
        int v = v0 + ty + r;
        int b = b0 + tx;
        if (v < N_NODES)
            g_xt[v * B_BATCH + b] = __float2half_rn(tile[tx][ty + r]);
    }
}

// ---------------------------------------------------------------------------
// 3. Edge scatter: 8 threads/edge, each handles 8 batches (16B fp16).
//    Per edge: 16 vector REDs (f16x2.v4) + 2 scalar col atomics.
//      msg_r[i][:] += w_r * x[j][:]    col_r[j] += w_r
//      msg_d[j][:] += w_d * x[i][:]    col_d[i] += w_d
// ---------------------------------------------------------------------------
__global__ void edge_kernel(const int* __restrict__ ei,
                            const int* __restrict__ ej,
                            const float* __restrict__ wr,
                            const float* __restrict__ wd) {
    long tid = (long)blockIdx.x * blockDim.x + threadIdx.x;
    int e = (int)(tid >> 3);
    int t = (int)(tid & 7);
    if (e >= E_EDGES) return;

    int i = ei[e];
    int j = ej[e];
    float w1 = wr[e];
    float w2 = wd[e];

    const uint4* rowj = reinterpret_cast<const uint4*>(g_xt + (size_t)j * B_BATCH);
    const uint4* rowi = reinterpret_cast<const uint4*>(g_xt + (size_t)i * B_BATCH);
    uint4 hj = rowj[t];
    uint4 hi = rowi[t];

    red_v4_f16x2(g_msg_r + (size_t)i * B_BATCH + t * 8, scale8h(hj, w1));
    red_v4_f16x2(g_msg_d + (size_t)j * B_BATCH + t * 8, scale8h(hi, w2));

    if (t == 0) {
        atomicAdd(&g_col_r[j], w1);
        atomicAdd(&g_col_d[i], w2);
    }
}

// ---------------------------------------------------------------------------
// 4. Epilogue: fp32 x from original input via smem transpose, fp16 msgs,
//    compute tanh(reaction)+diffusion+x, write out [B, N] coalesced.
// ---------------------------------------------------------------------------
__global__ void final_kernel(const float* __restrict__ x,
                             const float* __restrict__ bias_r,
                             const float* __restrict__ bias_d,
                             float* __restrict__ out) {
    __shared__ float sx[32 * 65];   // x tile, node-major
    __shared__ float so[32 * 65];   // out tile
    int V0 = blockIdx.x * 32;
    int tid = threadIdx.x;          // 0..511

    // load x tile coalesced: b = tid/8, vg = tid%8 (4 nodes each)
    {
        int b  = tid >> 3;
        int vg = tid & 7;
        int vbase = V0 + vg * 4;
        if (vbase + 3 < N_NODES) {
            float4 xv = *reinterpret_cast<const float4*>(&x[(long)b * N_NODES + vbase]);
            sx[(vg * 4 + 0) * 65 + b] = xv.x;
            sx[(vg * 4 + 1) * 65 + b] = xv.y;
            sx[(vg * 4 + 2) * 65 + b] = xv.z;
            sx[(vg * 4 + 3) * 65 + b] = xv.w;
        } else {
            for (int k = 0; k < 4 && vbase + k < N_NODES; k++)
                sx[(vg * 4 + k) * 65 + b] = x[(long)b * N_NODES + vbase + k];
        }
    }
    __syncthreads();

    // compute: vl = node in tile, q = 4-batch chunk
    {
        int vl = tid >> 4;
        int q  = tid & 15;
        int v  = V0 + vl;
        if (v < N_NODES) {
            uint2 mr2 = *reinterpret_cast<const uint2*>(&g_msg_r[(size_t)v * B_BATCH + q * 4]);
            uint2 md2 = *reinterpret_cast<const uint2*>(&g_msg_d[(size_t)v * B_BATCH + q * 4]);
            float2 mra = __half22float2(*reinterpret_cast<__half2*>(&mr2.x));
            float2 mrb = __half22float2(*reinterpret_cast<__half2*>(&mr2.y));
            float2 mda = __half22float2(*reinterpret_cast<__half2*>(&md2.x));
            float2 mdb = __half22float2(*reinterpret_cast<__half2*>(&md2.y));
            float cr = g_col_r[v];
            float cd = g_col_d[v];
            float b1 = bias_r[v];
            float b2 = bias_d[v];
            float ms[4] = {mra.x, mra.y, mrb.x, mrb.y};
            float dd[4] = {mda.x, mda.y, mdb.x, mdb.y};
            #pragma unroll
            for (int k = 0; k < 4; k++) {
                float xv = sx[vl * 65 + q * 4 + k];
                float reac = fmaf(cr, xv, -ms[k]) + b1;
                float diff = fmaf(cd, xv, -dd[k]) + b2;
                so[vl * 65 + q * 4 + k] = tanhf(reac) + diff + xv;
            }
        }
    }
    __syncthreads();

    // write out coalesced float4 along v
    {
        int b  = tid >> 3;
        int vg = tid & 7;
        int vbase = V0 + vg * 4;
        if (vbase + 3 < N_NODES) {
            float4 o;
            o.x = so[(vg * 4 + 0) * 65 + b];
            o.y = so[(vg * 4 + 1) * 65 + b];
            o.z = so[(vg * 4 + 2) * 65 + b];
            o.w = so[(vg * 4 + 3) * 65 + b];
            *reinterpret_cast<float4*>(&out[(long)b * N_NODES + vbase]) = o;
        } else if (vbase < N_NODES) {
            for (int k = 0; k < 4 && vbase + k < N_NODES; k++)
                out[(long)b * N_NODES + vbase + k] = so[(vg * 4 + k) * 65 + b];
        }
    }
}

// ---------------------------------------------------------------------------
extern "C" void kernel_launch(void* const* d_in, const int* in_sizes, int n_in,
                              void* d_out, int out_size) {
    // order: t, input, edge_i, edge_j, weight_react, weight_diff,
    //        bias_reaction, bias_diffusion
    const float* x  = (const float*)d_in[1];
    const int*   ei = (const int*)d_in[2];
    const int*   ej = (const int*)d_in[3];
    const float* wr = (const float*)d_in[4];
    const float* wd = (const float*)d_in[5];
    const float* br = (const float*)d_in[6];
    const float* bd = (const float*)d_in[7];
    float* out = (float*)d_out;

    int zero_threads = 2 * (NB / 8) + 2 * N_NODES;
    zero_kernel<<<(zero_threads + 255) / 256, 256>>>();

    dim3 tg((N_NODES + 31) / 32, B_BATCH / 32);
    transpose_kernel<<<tg, dim3(32, 8)>>>(x);

    long edge_threads = (long)E_EDGES * 8;
    edge_kernel<<<(unsigned)((edge_threads + 255) / 256), 256>>>(ei, ej, wr, wd);

    final_kernel<<<(N_NODES + 31) / 32, 512>>>(x, br, bd, out);
}

// round 9
// speedup vs baseline: 2.5319x; 1.0686x over previous
#include <cuda_runtime.h>
#include <cuda_fp16.h>
#include <math.h>

#define N_NODES 50000
#define E_EDGES 1600000
#define B_BATCH 64
#define NB (N_NODES * B_BATCH)

// ---------------------------------------------------------------------------
// Scratch (__device__ globals; allocation-free). All fp16, 16B-aligned for
// uint4 loads and red.global.add.noftz.v4.f16x2 (misalign = err715 trap).
// ---------------------------------------------------------------------------
__device__ __align__(16) __half g_xt[NB];      // x node-major fp16 [N][64]
__device__ __align__(16) __half g_msg_r[NB];   // reaction messages  (fp16 accum)
__device__ __align__(16) __half g_msg_d[NB];   // diffusion messages (fp16 accum)
__device__ float g_col_r[N_NODES];
__device__ float g_col_d[N_NODES];

__device__ __forceinline__ void red_v4_f16x2(__half* p, uint4 v) {
    unsigned long long gp;
    asm("cvta.to.global.u64 %0, %1;" : "=l"(gp) : "l"(p));
    asm volatile("red.global.add.noftz.v4.f16x2 [%0], {%1,%2,%3,%4};"
                 :: "l"(gp), "r"(v.x), "r"(v.y), "r"(v.z), "r"(v.w)
                 : "memory");
}

// scale 8 halves (uint4) by fp32 w, fp32 intermediate math, repack to f16x2
__device__ __forceinline__ uint4 scale8h(uint4 h, float w) {
    uint4 r;
    const unsigned* hp = &h.x;
    unsigned* rp = &r.x;
    #pragma unroll
    for (int k = 0; k < 4; k++) {
        float2 f = __half22float2(*reinterpret_cast<const __half2*>(&hp[k]));
        f.x *= w; f.y *= w;
        *reinterpret_cast<__half2*>(&rp[k]) = __float22half2_rn(f);
    }
    return r;
}

__device__ __forceinline__ float tanh_fast(float v) {
    float r;
    asm("tanh.approx.f32 %0, %1;" : "=f"(r) : "f"(v));
    return r;
}

// ---------------------------------------------------------------------------
// 1. Fused: zero accumulators + transpose x [B,N] -> g_xt [N][64] fp16.
//    Zero phase uses the flat thread id (800256 threads >= 800000 uint4
//    stores + 100000 col floats). Independent buffers: no sync needed
//    between phases; the next kernel launch is the ordering point.
// ---------------------------------------------------------------------------
__global__ void transpose_zero_kernel(const float* __restrict__ x) {
    __shared__ float tile[32][33];
    int tx = threadIdx.x;   // 0..31
    int ty = threadIdx.y;   // 0..7
    int tid = ty * 32 + tx; // 0..255

    // ---- zero phase ----
    {
        const int Q = NB / 8;   // 400000 uint4 per msg buffer
        long flat = ((long)blockIdx.y * gridDim.x + blockIdx.x) * 256 + tid;
        uint4 z = make_uint4(0, 0, 0, 0);
        if (flat < Q) {
            reinterpret_cast<uint4*>(g_msg_r)[flat] = z;
        } else if (flat < 2 * Q) {
            reinterpret_cast<uint4*>(g_msg_d)[flat - Q] = z;
        }
        if (flat < N_NODES) {
            g_col_r[flat] = 0.f;
            g_col_d[flat] = 0.f;
        }
    }

    // ---- transpose phase ----
    int v0 = blockIdx.x * 32;
    int b0 = blockIdx.y * 32;

    #pragma unroll
    for (int r = 0; r < 32; r += 8) {
        int b = b0 + ty + r;
        int v = v0 + tx;
        if (v < N_NODES)
            tile[ty + r][tx] = x[(long)b * N_NODES + v];
    }
    __syncthreads();
    #pragma unroll
    for (int r = 0; r < 32; r += 8) {
        int v = v0 + ty + r;
        int b = b0 + tx;
        if (v < N_NODES)
            g_xt[v * B_BATCH + b] = __float2half_rn(tile[tx][ty + r]);
    }
}

// ---------------------------------------------------------------------------
// 2. Edge scatter: 8 threads/edge, each handles 8 batches (16B fp16).
//    Per edge: 16 vector REDs (f16x2.v4) + 2 scalar col atomics.
//      msg_r[i][:] += w_r * x[j][:]    col_r[j] += w_r
//      msg_d[j][:] += w_d * x[i][:]    col_d[i] += w_d
// ---------------------------------------------------------------------------
__global__ void edge_kernel(const int* __restrict__ ei,
                            const int* __restrict__ ej,
                            const float* __restrict__ wr,
                            const float* __restrict__ wd) {
    long tid = (long)blockIdx.x * blockDim.x + threadIdx.x;
    int e = (int)(tid >> 3);
    int t = (int)(tid & 7);
    if (e >= E_EDGES) return;

    int i = ei[e];
    int j = ej[e];
    float w1 = wr[e];
    float w2 = wd[e];

    const uint4* rowj = reinterpret_cast<const uint4*>(g_xt + (size_t)j * B_BATCH);
    const uint4* rowi = reinterpret_cast<const uint4*>(g_xt + (size_t)i * B_BATCH);
    uint4 hj = rowj[t];
    uint4 hi = rowi[t];

    red_v4_f16x2(g_msg_r + (size_t)i * B_BATCH + t * 8, scale8h(hj, w1));
    red_v4_f16x2(g_msg_d + (size_t)j * B_BATCH + t * 8, scale8h(hi, w2));

    if (t == 0) {
        atomicAdd(&g_col_r[j], w1);
        atomicAdd(&g_col_d[i], w2);
    }
}

// ---------------------------------------------------------------------------
// 3. Epilogue: fp32 x from original input via smem transpose, fp16 msgs,
//    compute tanh(reaction)+diffusion+x, write out [B, N] coalesced.
// ---------------------------------------------------------------------------
__global__ void final_kernel(const float* __restrict__ x,
                             const float* __restrict__ bias_r,
                             const float* __restrict__ bias_d,
                             float* __restrict__ out) {
    __shared__ float sx[32 * 65];   // x tile, node-major
    __shared__ float so[32 * 65];   // out tile
    int V0 = blockIdx.x * 32;
    int tid = threadIdx.x;          // 0..511

    // load x tile coalesced: b = tid/8, vg = tid%8 (4 nodes each)
    {
        int b  = tid >> 3;
        int vg = tid & 7;
        int vbase = V0 + vg * 4;
        if (vbase + 3 < N_NODES) {
            float4 xv = *reinterpret_cast<const float4*>(&x[(long)b * N_NODES + vbase]);
            sx[(vg * 4 + 0) * 65 + b] = xv.x;
            sx[(vg * 4 + 1) * 65 + b] = xv.y;
            sx[(vg * 4 + 2) * 65 + b] = xv.z;
            sx[(vg * 4 + 3) * 65 + b] = xv.w;
        } else {
            for (int k = 0; k < 4 && vbase + k < N_NODES; k++)
                sx[(vg * 4 + k) * 65 + b] = x[(long)b * N_NODES + vbase + k];
        }
    }
    __syncthreads();

    // compute: vl = node in tile, q = 4-batch chunk
    {
        int vl = tid >> 4;
        int q  = tid & 15;
        int v  = V0 + vl;
        if (v < N_NODES) {
            uint2 mr2 = *reinterpret_cast<const uint2*>(&g_msg_r[(size_t)v * B_BATCH + q * 4]);
            uint2 md2 = *reinterpret_cast<const uint2*>(&g_msg_d[(size_t)v * B_BATCH + q * 4]);
            float2 mra = __half22float2(*reinterpret_cast<__half2*>(&mr2.x));
            float2 mrb = __half22float2(*reinterpret_cast<__half2*>(&mr2.y));
            float2 mda = __half22float2(*reinterpret_cast<__half2*>(&md2.x));
            float2 mdb = __half22float2(*reinterpret_cast<__half2*>(&md2.y));
            float cr = g_col_r[v];
            float cd = g_col_d[v];
            float b1 = bias_r[v];
            float b2 = bias_d[v];
            float ms[4] = {mra.x, mra.y, mrb.x, mrb.y};
            float dd[4] = {mda.x, mda.y, mdb.x, mdb.y};
            #pragma unroll
            for (int k = 0; k < 4; k++) {
                float xv = sx[vl * 65 + q * 4 + k];
                float reac = fmaf(cr, xv, -ms[k]) + b1;
                float diff = fmaf(cd, xv, -dd[k]) + b2;
                so[vl * 65 + q * 4 + k] = tanh_fast(reac) + diff + xv;
            }
        }
    }
    __syncthreads();

    // write out coalesced float4 along v
    {
        int b  = tid >> 3;
        int vg = tid & 7;
        int vbase = V0 + vg * 4;
        if (vbase + 3 < N_NODES) {
            float4 o;
            o.x = so[(vg * 4 + 0) * 65 + b];
            o.y = so[(vg * 4 + 1) * 65 + b];
            o.z = so[(vg * 4 + 2) * 65 + b];
            o.w = so[(vg * 4 + 3) * 65 + b];
            *reinterpret_cast<float4*>(&out[(long)b * N_NODES + vbase]) = o;
        } else if (vbase < N_NODES) {
            for (int k = 0; k < 4 && vbase + k < N_NODES; k++)
                out[(long)b * N_NODES + vbase + k] = so[(vg * 4 + k) * 65 + b];
        }
    }
}

// ---------------------------------------------------------------------------
extern "C" void kernel_launch(void* const* d_in, const int* in_sizes, int n_in,
                              void* d_out, int out_size) {
    // order: t, input, edge_i, edge_j, weight_react, weight_diff,
    //        bias_reaction, bias_diffusion
    const float* x  = (const float*)d_in[1];
    const int*   ei = (const int*)d_in[2];
    const int*   ej = (const int*)d_in[3];
    const float* wr = (const float*)d_in[4];
    const float* wd = (const float*)d_in[5];
    const float* br = (const float*)d_in[6];
    const float* bd = (const float*)d_in[7];
    float* out = (float*)d_out;

    dim3 tg((N_NODES + 31) / 32, B_BATCH / 32);   // 1563 x 2 blocks, 256 thr
    transpose_zero_kernel<<<tg, dim3(32, 8)>>>(x);

    long edge_threads = (long)E_EDGES * 8;
    edge_kernel<<<(unsigned)((edge_threads + 255) / 256), 256>>>(ei, ej, wr, wd);

    final_kernel<<<(N_NODES + 31) / 32, 512>>>(x, br, bd, out);
}